// round 1
// baseline (speedup 1.0000x reference)
#include <cuda_runtime.h>
#include <math.h>

#define B_ 32
#define C_ 128
#define H_ 128
#define W_ 128
#define K_ 4
#define O_ 128

// ---------------- scratch (no allocations allowed) ----------------
__device__ float g_pooled[B_ * C_];          // [b][c]
__device__ float g_attn[B_ * K_];            // [b][k]
__device__ float g_aggw[(size_t)B_ * C_ * 9 * O_];   // [b][c][rs][o]  (18 MB)
__device__ float g_aggb[B_ * O_];            // [b][o]

// ---------------- 1) global average pool ----------------
// one block per (b,c); 256 threads reduce 16384 floats
__global__ __launch_bounds__(256) void pool_kernel(const float* __restrict__ x) {
    int bc = blockIdx.x;                     // b*C + c
    const float4* p = (const float4*)(x + (size_t)bc * H_ * W_);
    float s = 0.f;
    for (int i = threadIdx.x; i < (H_ * W_) / 4; i += 256) {
        float4 v = p[i];
        s += (v.x + v.y) + (v.z + v.w);
    }
    // warp reduce
    #pragma unroll
    for (int off = 16; off > 0; off >>= 1)
        s += __shfl_down_sync(0xffffffffu, s, off);
    __shared__ float red[8];
    int lane = threadIdx.x & 31, wid = threadIdx.x >> 5;
    if (lane == 0) red[wid] = s;
    __syncthreads();
    if (wid == 0) {
        float t = (lane < 8) ? red[lane] : 0.f;
        #pragma unroll
        for (int off = 4; off > 0; off >>= 1)
            t += __shfl_down_sync(0xffffffffu, t, off);
        if (lane == 0) g_pooled[bc] = t * (1.0f / (H_ * W_));
    }
}

// ---------------- 2) attention MLP + softmax + agg_b ----------------
// 32 threads, one per batch sample
__global__ void attn_kernel(const float* __restrict__ w1, const float* __restrict__ b1,
                            const float* __restrict__ w2, const float* __restrict__ b2,
                            const float* __restrict__ bias) {
    int b = threadIdx.x;
    if (b >= B_) return;
    float h[K_];
    #pragma unroll
    for (int k = 0; k < K_; k++) {
        float s = b1[k];
        for (int c = 0; c < C_; c++)
            s += g_pooled[b * C_ + c] * w1[k * C_ + c];
        h[k] = fmaxf(s, 0.f);
    }
    float lg[K_];
    #pragma unroll
    for (int j = 0; j < K_; j++) {
        float s = b2[j];
        #pragma unroll
        for (int k = 0; k < K_; k++) s += h[k] * w2[j * K_ + k];
        lg[j] = s;
    }
    float m = lg[0];
    #pragma unroll
    for (int j = 1; j < K_; j++) m = fmaxf(m, lg[j]);
    float den = 0.f, e[K_];
    #pragma unroll
    for (int j = 0; j < K_; j++) { e[j] = __expf(lg[j] - m); den += e[j]; }
    float a[K_];
    #pragma unroll
    for (int j = 0; j < K_; j++) { a[j] = e[j] / den; g_attn[b * K_ + j] = a[j]; }
    // aggregated bias
    for (int o = 0; o < O_; o++) {
        float s = 0.f;
        #pragma unroll
        for (int k = 0; k < K_; k++) s += a[k] * bias[k * O_ + o];
        g_aggb[b * O_ + o] = s;
    }
}

// ---------------- 3) weight aggregation ----------------
// g_aggw[b][c][rs][o] = sum_k attn[b][k] * weight[k][o][c][rs]
__global__ __launch_bounds__(256) void aggw_kernel(const float* __restrict__ weight) {
    size_t i = (size_t)blockIdx.x * 256 + threadIdx.x;
    const size_t total = (size_t)B_ * C_ * 9 * O_;
    if (i >= total) return;
    int o  = (int)(i % O_);
    int rs = (int)((i / O_) % 9);
    int c  = (int)((i / ((size_t)O_ * 9)) % C_);
    int b  = (int)(i / ((size_t)O_ * 9 * C_));
    const size_t kstride = (size_t)O_ * C_ * 9;
    size_t widx = (((size_t)o * C_) + c) * 9 + rs;
    float a0 = g_attn[b * K_ + 0];
    float a1 = g_attn[b * K_ + 1];
    float a2 = g_attn[b * K_ + 2];
    float a3 = g_attn[b * K_ + 3];
    float v = a0 * __ldg(weight + widx)
            + a1 * __ldg(weight + widx + kstride)
            + a2 * __ldg(weight + widx + 2 * kstride)
            + a3 * __ldg(weight + widx + 3 * kstride);
    g_aggw[i] = v;
}

// ---------------- 4) direct conv, implicit GEMM ----------------
// block: (b, 8x8 spatial tile), all 128 output channels.
// 256 threads: thread tile = 8 o x 4 pixels (32 accumulators).
// smem: weight chunk [8c][9][128o] = 36 KB (contiguous from g_aggw),
//       x halo      [8c][10 x 10] stride-13 padded = 4.1 KB (conflict-free).
__global__ __launch_bounds__(256) void conv_kernel(const float* __restrict__ x,
                                                   float* __restrict__ out) {
    __shared__ float sW[8 * 9 * O_];   // [cc][rs][o]
    __shared__ float sX[8 * 130];      // [cc][iy*13 + ix], 10x10 valid

    const int b   = blockIdx.y;
    const int ty  = blockIdx.x >> 4;
    const int tx  = blockIdx.x & 15;
    const int y0  = ty * 8;
    const int x0  = tx * 8;
    const int tid = threadIdx.x;

    const int og    = tid >> 4;            // 0..15 -> o base = og*8
    const int pg    = tid & 15;            // 0..15 -> pixel group
    const int py    = pg >> 1;             // row 0..7
    const int px    = (pg & 1) * 4;        // col 0 or 4
    const int obase = og * 8;

    float acc[8][4];
    #pragma unroll
    for (int i = 0; i < 8; i++)
        #pragma unroll
        for (int j = 0; j < 4; j++) acc[i][j] = 0.f;

    const float* wg = g_aggw + (size_t)b * C_ * 9 * O_;

    for (int ct = 0; ct < C_; ct += 8) {
        __syncthreads();
        // ---- stage weights: 9216 floats contiguous -> 2304 float4 ----
        {
            const float4* wsrc = (const float4*)(wg + (size_t)ct * 9 * O_);
            float4* wdst = (float4*)sW;
            #pragma unroll
            for (int i = 0; i < 9; i++)
                wdst[tid + i * 256] = wsrc[tid + i * 256];
        }
        // ---- stage x halo: 8 channels x 10x10 (zero padded) ----
        for (int i = tid; i < 800; i += 256) {
            int cc  = i / 100;
            int rem = i - cc * 100;
            int iy  = rem / 10;
            int ix  = rem - iy * 10;
            int gy  = y0 + iy - 1;
            int gx  = x0 + ix - 1;
            float v = 0.f;
            if (gy >= 0 && gy < H_ && gx >= 0 && gx < W_)
                v = x[(((size_t)b * C_ + ct + cc) * H_ + gy) * W_ + gx];
            sX[cc * 130 + iy * 13 + ix] = v;
        }
        __syncthreads();

        #pragma unroll 2
        for (int cc = 0; cc < 8; cc++) {
            const float* xp = &sX[cc * 130 + py * 13 + px];
            const float* wp = &sW[cc * 9 * O_ + obase];
            #pragma unroll
            for (int r = 0; r < 3; r++) {
                #pragma unroll
                for (int s = 0; s < 3; s++) {
                    float xv[4];
                    #pragma unroll
                    for (int j = 0; j < 4; j++)
                        xv[j] = xp[r * 13 + s + j];
                    const float4 wa = *(const float4*)(wp + (r * 3 + s) * O_);
                    const float4 wb = *(const float4*)(wp + (r * 3 + s) * O_ + 4);
                    float wv[8] = {wa.x, wa.y, wa.z, wa.w, wb.x, wb.y, wb.z, wb.w};
                    #pragma unroll
                    for (int i = 0; i < 8; i++)
                        #pragma unroll
                        for (int j = 0; j < 4; j++)
                            acc[i][j] = fmaf(wv[i], xv[j], acc[i][j]);
                }
            }
        }
    }

    // ---- epilogue: add agg_b, float4 stores ----
    #pragma unroll
    for (int i = 0; i < 8; i++) {
        int o = obase + i;
        float bb = g_aggb[b * O_ + o];
        float4 v = make_float4(acc[i][0] + bb, acc[i][1] + bb,
                               acc[i][2] + bb, acc[i][3] + bb);
        *(float4*)&out[(((size_t)b * O_ + o) * H_ + (y0 + py)) * W_ + x0 + px] = v;
    }
}

// ---------------- launch ----------------
extern "C" void kernel_launch(void* const* d_in, const int* in_sizes, int n_in,
                              void* d_out, int out_size) {
    const float* x      = (const float*)d_in[0];
    const float* att_w1 = (const float*)d_in[1];
    const float* att_b1 = (const float*)d_in[2];
    const float* att_w2 = (const float*)d_in[3];
    const float* att_b2 = (const float*)d_in[4];
    const float* weight = (const float*)d_in[5];
    const float* bias   = (const float*)d_in[6];
    float* out = (float*)d_out;

    pool_kernel<<<B_ * C_, 256>>>(x);
    attn_kernel<<<1, 32>>>(att_w1, att_b1, att_w2, att_b2, bias);
    {
        const size_t total = (size_t)B_ * C_ * 9 * O_;
        aggw_kernel<<<(unsigned)((total + 255) / 256), 256>>>(weight);
    }
    {
        dim3 grid(256, B_);   // 16x16 spatial tiles, per-batch
        conv_kernel<<<grid, 256>>>(x, out);
    }
}

// round 3
// speedup vs baseline: 5.2445x; 5.2445x over previous
#include <cuda_runtime.h>
#include <cuda_fp16.h>
#include <cstdint>

#define B_ 32
#define C_ 128
#define H_ 128
#define W_ 128
#define K_ 4
#define O_ 128
#define RS_ 9

// ---------------- scratch ----------------
__device__ float  g_pooled[B_ * C_];
__device__ float  g_attn[B_ * K_];
__device__ float  g_aggb[B_ * O_];
__device__ __half g_aggw16[(size_t)B_ * RS_ * O_ * C_];      // [b][rs][o][c]  9.4 MB
__device__ __half g_xT[(size_t)B_ * H_ * W_ * C_];           // [b][y][p][c]   128 MB NHWC fp16

// ---------------- helpers ----------------
__device__ __forceinline__ uint32_t smem_u32(const void* p) {
    uint32_t a;
    asm("{ .reg .u64 t; cvta.to.shared.u64 t, %1; cvt.u32.u64 %0, t; }" : "=r"(a) : "l"(p));
    return a;
}
__device__ __forceinline__ void cp16(uint32_t dst, const void* src, int srcsize) {
    asm volatile("cp.async.cg.shared.global [%0], [%1], 16, %2;"
                 :: "r"(dst), "l"(src), "r"(srcsize) : "memory");
}
#define CP_COMMIT() asm volatile("cp.async.commit_group;" ::: "memory")

__device__ __forceinline__ void ldmat_x4(uint32_t* r, uint32_t addr) {
    asm volatile("ldmatrix.sync.aligned.m8n8.x4.shared.b16 {%0,%1,%2,%3}, [%4];"
                 : "=r"(r[0]), "=r"(r[1]), "=r"(r[2]), "=r"(r[3]) : "r"(addr));
}
__device__ __forceinline__ void ldmat_x2(uint32_t* r, uint32_t addr) {
    asm volatile("ldmatrix.sync.aligned.m8n8.x2.shared.b16 {%0,%1}, [%2];"
                 : "=r"(r[0]), "=r"(r[1]) : "r"(addr));
}
__device__ __forceinline__ void mma16816(float* c, const uint32_t* a, const uint32_t* b) {
    asm volatile("mma.sync.aligned.m16n8k16.row.col.f32.f16.f16.f32 "
                 "{%0,%1,%2,%3}, {%4,%5,%6,%7}, {%8,%9}, {%0,%1,%2,%3};"
                 : "+f"(c[0]), "+f"(c[1]), "+f"(c[2]), "+f"(c[3])
                 : "r"(a[0]), "r"(a[1]), "r"(a[2]), "r"(a[3]), "r"(b[0]), "r"(b[1]));
}

// ---------------- 1) global average pool ----------------
__global__ __launch_bounds__(256) void pool_kernel(const float* __restrict__ x) {
    int bc = blockIdx.x;
    const float4* p = (const float4*)(x + (size_t)bc * H_ * W_);
    float s = 0.f;
    for (int i = threadIdx.x; i < (H_ * W_) / 4; i += 256) {
        float4 v = p[i];
        s += (v.x + v.y) + (v.z + v.w);
    }
    #pragma unroll
    for (int off = 16; off > 0; off >>= 1) s += __shfl_down_sync(0xffffffffu, s, off);
    __shared__ float red[8];
    int lane = threadIdx.x & 31, wid = threadIdx.x >> 5;
    if (lane == 0) red[wid] = s;
    __syncthreads();
    if (wid == 0) {
        float t = (lane < 8) ? red[lane] : 0.f;
        #pragma unroll
        for (int off = 4; off > 0; off >>= 1) t += __shfl_down_sync(0xffffffffu, t, off);
        if (lane == 0) g_pooled[bc] = t * (1.0f / (H_ * W_));
    }
}

// ---------------- 2) attention MLP + softmax + agg_b ----------------
__global__ void attn_kernel(const float* __restrict__ w1, const float* __restrict__ b1,
                            const float* __restrict__ w2, const float* __restrict__ b2,
                            const float* __restrict__ bias) {
    int b = threadIdx.x;
    if (b >= B_) return;
    float h[K_];
    #pragma unroll
    for (int k = 0; k < K_; k++) {
        float s = b1[k];
        for (int c = 0; c < C_; c++) s += g_pooled[b * C_ + c] * w1[k * C_ + c];
        h[k] = fmaxf(s, 0.f);
    }
    float lg[K_];
    #pragma unroll
    for (int j = 0; j < K_; j++) {
        float s = b2[j];
        #pragma unroll
        for (int k = 0; k < K_; k++) s += h[k] * w2[j * K_ + k];
        lg[j] = s;
    }
    float m = lg[0];
    #pragma unroll
    for (int j = 1; j < K_; j++) m = fmaxf(m, lg[j]);
    float den = 0.f, e[K_];
    #pragma unroll
    for (int j = 0; j < K_; j++) { e[j] = __expf(lg[j] - m); den += e[j]; }
    float a[K_];
    #pragma unroll
    for (int j = 0; j < K_; j++) { a[j] = e[j] / den; g_attn[b * K_ + j] = a[j]; }
    for (int o = 0; o < O_; o++) {
        float s = 0.f;
        #pragma unroll
        for (int k = 0; k < K_; k++) s += a[k] * bias[k * O_ + o];
        g_aggb[b * O_ + o] = s;
    }
}

// ---------------- 3) weight aggregation -> fp16 [b][rs][o][c] ----------------
__global__ __launch_bounds__(256) void aggw16_kernel(const float* __restrict__ weight) {
    int idx = blockIdx.x * 256 + threadIdx.x;   // 16384 = O_*C_
    int o = idx >> 7, c = idx & 127;
    float w[K_][RS_];
    #pragma unroll
    for (int k = 0; k < K_; k++) {
        const float* p = weight + ((size_t)(k * O_ + o) * C_ + c) * RS_;
        #pragma unroll
        for (int rs = 0; rs < RS_; rs++) w[k][rs] = p[rs];
    }
    for (int b = 0; b < B_; b++) {
        float a0 = g_attn[b * K_ + 0], a1 = g_attn[b * K_ + 1];
        float a2 = g_attn[b * K_ + 2], a3 = g_attn[b * K_ + 3];
        #pragma unroll
        for (int rs = 0; rs < RS_; rs++) {
            float s = a0 * w[0][rs] + a1 * w[1][rs] + a2 * w[2][rs] + a3 * w[3][rs];
            g_aggw16[(((size_t)b * RS_ + rs) * O_ + o) * C_ + c] = __float2half_rn(s);
        }
    }
}

// ---------------- 4) NCHW fp32 -> NHWC fp16 transpose ----------------
__global__ __launch_bounds__(256) void xT_kernel(const float* __restrict__ x) {
    __shared__ __half sA[8][64 * 33];
    int tid = threadIdx.x, w = tid >> 5, l = tid & 31;
    int by = blockIdx.x;              // b*128 + y
    int b = by >> 7, y = by & 127;
    int c0 = (w & 1) * 64, p0 = (w >> 1) * 32;
    __half* s = sA[w];
    #pragma unroll 4
    for (int i = 0; i < 64; i++) {
        float v = x[(((size_t)b * C_ + c0 + i) * H_ + y) * W_ + p0 + l];
        s[i * 33 + l] = __float2half_rn(v);
    }
    __syncwarp();
    #pragma unroll 4
    for (int i = 0; i < 32; i++) {
        __half2 hv = __halves2half2(s[(2 * l) * 33 + i], s[(2 * l + 1) * 33 + i]);
        *(__half2*)(g_xT + (((size_t)b * H_ + y) * W_ + p0 + i) * C_ + c0 + 2 * l) = hv;
    }
}

// ---------------- 5) HMMA implicit-GEMM conv ----------------
// CTA = (y, b). D[o=128][pix=128] = sum_rs A_rs[o][c] * B_rs[pix][c]^T.
// smem: A double buffer 2 x (128 rows x 272B) + B 3 rows x 130 pix x 272B.
#define A_STRIDE 272
#define A_BYTES  (128 * A_STRIDE)            // 34816
#define SM_B_OFF (2 * A_BYTES)               // 69632
#define B_ROW    (130 * A_STRIDE)            // 35360
#define SMEM_CONV (SM_B_OFF + 3 * B_ROW)     // 175712

__global__ void __launch_bounds__(256, 1) conv_hmma(float* __restrict__ out) {
    extern __shared__ char smem[];
    const uint32_t sb = smem_u32(smem);
    const int tid = threadIdx.x, lane = tid & 31, wid = tid >> 5;
    const int b = blockIdx.y, y0 = blockIdx.x;
    const int wm = wid & 1;        // 0/1 -> o base 0/64
    const int wn = wid >> 1;       // 0..3 -> pix base wn*32

    // ---- B staging: 3 input rows x 130 pixels x 128c fp16 (zfill halo) ----
    for (int i = tid; i < 6240; i += 256) {       // 3 * 130 * 16 chunks of 16B
        int rr = i / 2080, rem = i - rr * 2080;
        int p = rem >> 4, ch = rem & 15;
        int y = y0 - 1 + rr, px = p - 1;
        bool ok = (y >= 0) & (y < H_) & (px >= 0) & (px < W_);
        uint32_t dst = sb + SM_B_OFF + rr * B_ROW + p * A_STRIDE + ch * 16;
        const __half* src = g_xT + ((((size_t)b * H_ + (ok ? y : 0)) * W_ + (ok ? px : 0)) * C_ + ch * 8);
        cp16(dst, src, ok ? 16 : 0);
    }
    // ---- A prefetch rs=0 (same group as B) ----
    {
        const __half* asrc = g_aggw16 + ((size_t)b * RS_ + 0) * O_ * C_;
        for (int i = tid; i < 2048; i += 256) {
            int o = i >> 4, ch = i & 15;
            cp16(sb + o * A_STRIDE + ch * 16, asrc + (size_t)o * C_ + ch * 8, 16);
        }
    }
    CP_COMMIT();
    // ---- A prefetch rs=1 ----
    {
        const __half* asrc = g_aggw16 + ((size_t)b * RS_ + 1) * O_ * C_;
        for (int i = tid; i < 2048; i += 256) {
            int o = i >> 4, ch = i & 15;
            cp16(sb + A_BYTES + o * A_STRIDE + ch * 16, asrc + (size_t)o * C_ + ch * 8, 16);
        }
    }
    CP_COMMIT();

    float acc[4][4][4];
    #pragma unroll
    for (int mt = 0; mt < 4; mt++)
        #pragma unroll
        for (int nt = 0; nt < 4; nt++)
            #pragma unroll
            for (int j = 0; j < 4; j++) acc[mt][nt][j] = 0.f;

    // lane address pieces
    const int lAr = lane & 15;                 // A row within m16
    const int lAk = (lane >> 4) * 16;          // A k-half byte offset
    const int lBr = lane & 7;                  // B row within n8
    const int lBk = ((lane >> 3) & 1) * 16;    // B k-half byte offset

    for (int rs = 0; rs < 9; rs++) {
        if (rs < 8) asm volatile("cp.async.wait_group 1;" ::: "memory");
        else        asm volatile("cp.async.wait_group 0;" ::: "memory");
        __syncthreads();

        const uint32_t Ab = sb + (rs & 1) * A_BYTES;
        const int r = rs / 3, s = rs - 3 * r;
        const uint32_t Bb = sb + SM_B_OFF + r * B_ROW;
        const uint32_t Abase = Ab + (wm * 64 + lAr) * A_STRIDE + lAk;
        const uint32_t Bbase = Bb + (wn * 32 + lBr + s) * A_STRIDE + lBk;

        #pragma unroll
        for (int kc = 0; kc < 8; kc++) {
            uint32_t bf[4][2];
            #pragma unroll
            for (int nt = 0; nt < 4; nt++)
                ldmat_x2(bf[nt], Bbase + nt * 8 * A_STRIDE + kc * 32);
            #pragma unroll
            for (int mt = 0; mt < 4; mt++) {
                uint32_t af[4];
                ldmat_x4(af, Abase + mt * 16 * A_STRIDE + kc * 32);
                #pragma unroll
                for (int nt = 0; nt < 4; nt++)
                    mma16816(acc[mt][nt], af, bf[nt]);
            }
        }
        __syncthreads();
        if (rs + 2 < 9) {
            const __half* asrc = g_aggw16 + ((size_t)b * RS_ + rs + 2) * O_ * C_;
            uint32_t dbuf = sb + (rs & 1) * A_BYTES;
            for (int i = tid; i < 2048; i += 256) {
                int o = i >> 4, ch = i & 15;
                cp16(dbuf + o * A_STRIDE + ch * 16, asrc + (size_t)o * C_ + ch * 8, 16);
            }
            CP_COMMIT();
        }
    }

    // ---- epilogue: bias + stores ----
    const int g = lane >> 2, t4 = lane & 3;
    #pragma unroll
    for (int mt = 0; mt < 4; mt++) {
        int o_lo = wm * 64 + mt * 16 + g;
        float b_lo = g_aggb[b * O_ + o_lo];
        float b_hi = g_aggb[b * O_ + o_lo + 8];
        float* p_lo = out + ((size_t)(b * O_ + o_lo) * H_ + y0) * W_;
        float* p_hi = p_lo + (size_t)8 * H_ * W_;
        #pragma unroll
        for (int nt = 0; nt < 4; nt++) {
            int xp = wn * 32 + nt * 8 + t4 * 2;
            float2 vlo = make_float2(acc[mt][nt][0] + b_lo, acc[mt][nt][1] + b_lo);
            float2 vhi = make_float2(acc[mt][nt][2] + b_hi, acc[mt][nt][3] + b_hi);
            *(float2*)(p_lo + xp) = vlo;
            *(float2*)(p_hi + xp) = vhi;
        }
    }
}

// ---------------- launch ----------------
extern "C" void kernel_launch(void* const* d_in, const int* in_sizes, int n_in,
                              void* d_out, int out_size) {
    const float* x      = (const float*)d_in[0];
    const float* att_w1 = (const float*)d_in[1];
    const float* att_b1 = (const float*)d_in[2];
    const float* att_w2 = (const float*)d_in[3];
    const float* att_b2 = (const float*)d_in[4];
    const float* weight = (const float*)d_in[5];
    const float* bias   = (const float*)d_in[6];
    float* out = (float*)d_out;

    cudaFuncSetAttribute(conv_hmma, cudaFuncAttributeMaxDynamicSharedMemorySize, SMEM_CONV);

    xT_kernel<<<B_ * H_, 256>>>(x);
    pool_kernel<<<B_ * C_, 256>>>(x);
    attn_kernel<<<1, 32>>>(att_w1, att_b1, att_w2, att_b2, bias);
    aggw16_kernel<<<64, 256>>>(weight);
    conv_hmma<<<dim3(H_, B_), 256, SMEM_CONV>>>(out);
}

// round 4
// speedup vs baseline: 6.2596x; 1.1936x over previous
#include <cuda_runtime.h>
#include <cuda_fp16.h>
#include <cstdint>

#define B_ 32
#define C_ 128
#define H_ 128
#define W_ 128
#define K_ 4
#define O_ 128
#define RS_ 9

// ---------------- scratch ----------------
__device__ float  g_poolrow[(size_t)B_ * H_ * C_];           // per-row channel sums
__device__ float  g_pooled[B_ * C_];
__device__ float  g_attn[B_ * K_];
__device__ float  g_aggb[B_ * O_];
__device__ __half g_aggw16[(size_t)B_ * RS_ * O_ * C_];      // [b][rs][o][c]
__device__ __half g_xT[(size_t)B_ * H_ * W_ * C_];           // [b][y][p][c] NHWC fp16

// ---------------- helpers ----------------
__device__ __forceinline__ uint32_t smem_u32(const void* p) {
    uint32_t a;
    asm("{ .reg .u64 t; cvta.to.shared.u64 t, %1; cvt.u32.u64 %0, t; }" : "=r"(a) : "l"(p));
    return a;
}
__device__ __forceinline__ void cp16(uint32_t dst, const void* src, int srcsize) {
    asm volatile("cp.async.cg.shared.global [%0], [%1], 16, %2;"
                 :: "r"(dst), "l"(src), "r"(srcsize) : "memory");
}
#define CP_COMMIT() asm volatile("cp.async.commit_group;" ::: "memory")

__device__ __forceinline__ void ldmat_x4(uint32_t* r, uint32_t addr) {
    asm volatile("ldmatrix.sync.aligned.m8n8.x4.shared.b16 {%0,%1,%2,%3}, [%4];"
                 : "=r"(r[0]), "=r"(r[1]), "=r"(r[2]), "=r"(r[3]) : "r"(addr));
}
__device__ __forceinline__ void mma16816(float* c, const uint32_t* a, const uint32_t* b) {
    asm volatile("mma.sync.aligned.m16n8k16.row.col.f32.f16.f16.f32 "
                 "{%0,%1,%2,%3}, {%4,%5,%6,%7}, {%8,%9}, {%0,%1,%2,%3};"
                 : "+f"(c[0]), "+f"(c[1]), "+f"(c[2]), "+f"(c[3])
                 : "r"(a[0]), "r"(a[1]), "r"(a[2]), "r"(a[3]), "r"(b[0]), "r"(b[1]));
}

// ---------------- 1) NCHW fp32 -> NHWC fp16 transpose + row pooling ----------------
__global__ __launch_bounds__(256) void xT_kernel(const float* __restrict__ x) {
    __shared__ __half sA[8][64 * 33];
    __shared__ float sPool[128];
    int tid = threadIdx.x, w = tid >> 5, l = tid & 31;
    int by = blockIdx.x;              // b*128 + y
    int b = by >> 7, y = by & 127;
    int c0 = (w & 1) * 64, p0 = (w >> 1) * 32;
    if (tid < 128) sPool[tid] = 0.f;
    __syncthreads();
    __half* s = sA[w];
    #pragma unroll 4
    for (int i = 0; i < 64; i++) {
        float v = x[(((size_t)b * C_ + c0 + i) * H_ + y) * W_ + p0 + l];
        s[i * 33 + l] = __float2half_rn(v);
    }
    __syncwarp();
    float s0 = 0.f, s1 = 0.f;
    #pragma unroll 4
    for (int i = 0; i < 32; i++) {
        __half h0 = s[(2 * l) * 33 + i], h1 = s[(2 * l + 1) * 33 + i];
        s0 += __half2float(h0);
        s1 += __half2float(h1);
        *(__half2*)(g_xT + (((size_t)b * H_ + y) * W_ + p0 + i) * C_ + c0 + 2 * l) =
            __halves2half2(h0, h1);
    }
    atomicAdd(&sPool[c0 + 2 * l], s0);
    atomicAdd(&sPool[c0 + 2 * l + 1], s1);
    __syncthreads();
    if (tid < 128)
        g_poolrow[((size_t)b * H_ + y) * C_ + tid] = sPool[tid];
}

// ---------------- 2) finish pooling ----------------
__global__ void pool2_kernel() {
    int b = blockIdx.x, c = threadIdx.x;
    const float* p = g_poolrow + (size_t)b * H_ * C_ + c;
    float s = 0.f;
    #pragma unroll 8
    for (int y = 0; y < H_; y++) s += p[(size_t)y * C_];
    g_pooled[b * C_ + c] = s * (1.0f / (H_ * W_));
}

// ---------------- 3) attention MLP + softmax + agg_b ----------------
__global__ void attn_kernel(const float* __restrict__ w1, const float* __restrict__ b1,
                            const float* __restrict__ w2, const float* __restrict__ b2,
                            const float* __restrict__ bias) {
    int b = threadIdx.x;
    if (b >= B_) return;
    float h[K_];
    #pragma unroll
    for (int k = 0; k < K_; k++) {
        float s = b1[k];
        for (int c = 0; c < C_; c++) s += g_pooled[b * C_ + c] * w1[k * C_ + c];
        h[k] = fmaxf(s, 0.f);
    }
    float lg[K_];
    #pragma unroll
    for (int j = 0; j < K_; j++) {
        float s = b2[j];
        #pragma unroll
        for (int k = 0; k < K_; k++) s += h[k] * w2[j * K_ + k];
        lg[j] = s;
    }
    float m = lg[0];
    #pragma unroll
    for (int j = 1; j < K_; j++) m = fmaxf(m, lg[j]);
    float den = 0.f, e[K_];
    #pragma unroll
    for (int j = 0; j < K_; j++) { e[j] = __expf(lg[j] - m); den += e[j]; }
    float a[K_];
    #pragma unroll
    for (int j = 0; j < K_; j++) { a[j] = e[j] / den; g_attn[b * K_ + j] = a[j]; }
    for (int o = 0; o < O_; o++) {
        float s = 0.f;
        #pragma unroll
        for (int k = 0; k < K_; k++) s += a[k] * bias[k * O_ + o];
        g_aggb[b * O_ + o] = s;
    }
}

// ---------------- 4) weight aggregation -> fp16 [b][rs][o][c] ----------------
__global__ __launch_bounds__(256) void aggw16_kernel(const float* __restrict__ weight) {
    int idx = blockIdx.x * 256 + threadIdx.x;   // 16384 = O_*C_
    int b = blockIdx.y;
    int o = idx >> 7, c = idx & 127;
    float a0 = g_attn[b * K_ + 0], a1 = g_attn[b * K_ + 1];
    float a2 = g_attn[b * K_ + 2], a3 = g_attn[b * K_ + 3];
    const float* p0 = weight + ((size_t)(0 * O_ + o) * C_ + c) * RS_;
    const float* p1 = weight + ((size_t)(1 * O_ + o) * C_ + c) * RS_;
    const float* p2 = weight + ((size_t)(2 * O_ + o) * C_ + c) * RS_;
    const float* p3 = weight + ((size_t)(3 * O_ + o) * C_ + c) * RS_;
    #pragma unroll
    for (int rs = 0; rs < RS_; rs++) {
        float s = a0 * p0[rs] + a1 * p1[rs] + a2 * p2[rs] + a3 * p3[rs];
        g_aggw16[(((size_t)b * RS_ + rs) * O_ + o) * C_ + c] = __float2half_rn(s);
    }
}

// ---------------- 5) HMMA implicit-GEMM conv, 2 output rows / CTA ----------------
// CTA = (y-pair, b). D[o=128][pix=256] = sum_rs A_rs[o][c] * B_rs[pix][c]^T.
// 8 warps: wm = wid&1 (o 0/64), wn = wid>>1 (pix base wn*64; wn>>1 selects out row).
#define A_STRIDE 272
#define A_BYTES  (128 * A_STRIDE)            // 34816
#define SM_B_OFF (2 * A_BYTES)               // 69632
#define B_ROW    (130 * A_STRIDE)            // 35360
#define SMEM_CONV (SM_B_OFF + 4 * B_ROW)     // 211072

__global__ void __launch_bounds__(256, 1) conv_hmma(float* __restrict__ out) {
    extern __shared__ char smem[];
    const uint32_t sb = smem_u32(smem);
    const int tid = threadIdx.x, lane = tid & 31, wid = tid >> 5;
    const int b = blockIdx.y, y0 = blockIdx.x * 2;
    const int wm = wid & 1;
    const int wn = wid >> 1;                  // 0..3
    const int h  = wn >> 1;                   // 0/1 output row select
    const int nb = (wn & 1) * 64;             // pixel col base

    // ---- B staging: 4 input rows x 130 pixels x 128c fp16 (zfill halo) ----
    for (int i = tid; i < 8320; i += 256) {       // 4 * 130 * 16 chunks of 16B
        int rr = i / 2080, rem = i - rr * 2080;
        int p = rem >> 4, ch = rem & 15;
        int y = y0 - 1 + rr, px = p - 1;
        bool ok = (y >= 0) & (y < H_) & (px >= 0) & (px < W_);
        uint32_t dst = sb + SM_B_OFF + rr * B_ROW + p * A_STRIDE + ch * 16;
        const __half* src = g_xT + ((((size_t)b * H_ + (ok ? y : 0)) * W_ + (ok ? px : 0)) * C_ + ch * 8);
        cp16(dst, src, ok ? 16 : 0);
    }
    // ---- A prefetch rs=0 (same group as B) ----
    {
        const __half* asrc = g_aggw16 + ((size_t)b * RS_ + 0) * O_ * C_;
        for (int i = tid; i < 2048; i += 256) {
            int o = i >> 4, ch = i & 15;
            cp16(sb + o * A_STRIDE + ch * 16, asrc + (size_t)o * C_ + ch * 8, 16);
        }
    }
    CP_COMMIT();
    // ---- A prefetch rs=1 ----
    {
        const __half* asrc = g_aggw16 + ((size_t)b * RS_ + 1) * O_ * C_;
        for (int i = tid; i < 2048; i += 256) {
            int o = i >> 4, ch = i & 15;
            cp16(sb + A_BYTES + o * A_STRIDE + ch * 16, asrc + (size_t)o * C_ + ch * 8, 16);
        }
    }
    CP_COMMIT();

    float acc[4][8][4];
    #pragma unroll
    for (int mt = 0; mt < 4; mt++)
        #pragma unroll
        for (int nt = 0; nt < 8; nt++)
            #pragma unroll
            for (int j = 0; j < 4; j++) acc[mt][nt][j] = 0.f;

    // lane address pieces
    const int lAr = lane & 15;                 // A row within m16
    const int lAk = (lane >> 4) * 16;          // A k-half byte offset
    const int lg  = lane >> 3;                 // B x4 group 0..3
    const int lr  = lane & 7;                  // B row within n8
    const int lBrow = (lg >> 1) * 8 + lr;      // row within 16-pixel pair
    const int lBk   = (lg & 1) * 16;           // B k-half byte offset

    for (int rs = 0; rs < 9; rs++) {
        if (rs < 8) asm volatile("cp.async.wait_group 1;" ::: "memory");
        else        asm volatile("cp.async.wait_group 0;" ::: "memory");
        __syncthreads();

        const uint32_t Ab = sb + (rs & 1) * A_BYTES;
        const int r = rs / 3, s = rs - 3 * r;
        const uint32_t Bbase = sb + SM_B_OFF + (r + h) * B_ROW
                             + (nb + lBrow + s) * A_STRIDE + lBk;
        const uint32_t Abase = Ab + (wm * 64 + lAr) * A_STRIDE + lAk;

        #pragma unroll
        for (int kc = 0; kc < 8; kc++) {
            uint32_t bf[8][2];
            #pragma unroll
            for (int nt2 = 0; nt2 < 4; nt2++) {
                uint32_t t[4];
                ldmat_x4(t, Bbase + nt2 * (16 * A_STRIDE) + kc * 32);
                bf[2 * nt2][0] = t[0]; bf[2 * nt2][1] = t[1];
                bf[2 * nt2 + 1][0] = t[2]; bf[2 * nt2 + 1][1] = t[3];
            }
            #pragma unroll
            for (int mt = 0; mt < 4; mt++) {
                uint32_t af[4];
                ldmat_x4(af, Abase + mt * 16 * A_STRIDE + kc * 32);
                #pragma unroll
                for (int nt = 0; nt < 8; nt++)
                    mma16816(acc[mt][nt], af, bf[nt]);
            }
        }
        __syncthreads();
        if (rs + 2 < 9) {
            const __half* asrc = g_aggw16 + ((size_t)b * RS_ + rs + 2) * O_ * C_;
            uint32_t dbuf = sb + (rs & 1) * A_BYTES;
            for (int i = tid; i < 2048; i += 256) {
                int o = i >> 4, ch = i & 15;
                cp16(dbuf + o * A_STRIDE + ch * 16, asrc + (size_t)o * C_ + ch * 8, 16);
            }
            CP_COMMIT();
        }
    }

    // ---- epilogue: bias + stores ----
    const int g = lane >> 2, t4 = lane & 3;
    const int yout = y0 + h;
    #pragma unroll
    for (int mt = 0; mt < 4; mt++) {
        int o_lo = wm * 64 + mt * 16 + g;
        float b_lo = g_aggb[b * O_ + o_lo];
        float b_hi = g_aggb[b * O_ + o_lo + 8];
        float* p_lo = out + ((size_t)(b * O_ + o_lo) * H_ + yout) * W_;
        float* p_hi = p_lo + (size_t)8 * H_ * W_;
        #pragma unroll
        for (int nt = 0; nt < 8; nt++) {
            int xp = nb + nt * 8 + t4 * 2;
            float2 vlo = make_float2(acc[mt][nt][0] + b_lo, acc[mt][nt][1] + b_lo);
            float2 vhi = make_float2(acc[mt][nt][2] + b_hi, acc[mt][nt][3] + b_hi);
            *(float2*)(p_lo + xp) = vlo;
            *(float2*)(p_hi + xp) = vhi;
        }
    }
}

// ---------------- launch ----------------
extern "C" void kernel_launch(void* const* d_in, const int* in_sizes, int n_in,
                              void* d_out, int out_size) {
    const float* x      = (const float*)d_in[0];
    const float* att_w1 = (const float*)d_in[1];
    const float* att_b1 = (const float*)d_in[2];
    const float* att_w2 = (const float*)d_in[3];
    const float* att_b2 = (const float*)d_in[4];
    const float* weight = (const float*)d_in[5];
    const float* bias   = (const float*)d_in[6];
    float* out = (float*)d_out;

    cudaFuncSetAttribute(conv_hmma, cudaFuncAttributeMaxDynamicSharedMemorySize, SMEM_CONV);

    xT_kernel<<<B_ * H_, 256>>>(x);
    pool2_kernel<<<B_, 128>>>();
    attn_kernel<<<1, 32>>>(att_w1, att_b1, att_w2, att_b2, bias);
    aggw16_kernel<<<dim3(64, B_), 256>>>(weight);
    conv_hmma<<<dim3(H_ / 2, B_), 256, SMEM_CONV>>>(out);
}

// round 5
// speedup vs baseline: 6.5191x; 1.0415x over previous
#include <cuda_runtime.h>
#include <cuda_fp16.h>
#include <cstdint>

#define B_ 32
#define C_ 128
#define H_ 128
#define W_ 128
#define K_ 4
#define O_ 128
#define RS_ 9

// ---------------- scratch ----------------
__device__ float  g_poolrow[(size_t)B_ * H_ * C_];           // per-row channel sums
__device__ float  g_attn[B_ * K_];
__device__ float  g_aggb[B_ * O_];
__device__ __half g_aggw16[(size_t)B_ * RS_ * O_ * C_];      // [b][rs][o][c]
__device__ __half g_xT[(size_t)B_ * H_ * W_ * C_];           // [b][y][p][c] NHWC fp16

// ---------------- helpers ----------------
__device__ __forceinline__ uint32_t smem_u32(const void* p) {
    uint32_t a;
    asm("{ .reg .u64 t; cvta.to.shared.u64 t, %1; cvt.u32.u64 %0, t; }" : "=r"(a) : "l"(p));
    return a;
}
__device__ __forceinline__ void cp16(uint32_t dst, const void* src, int srcsize) {
    asm volatile("cp.async.cg.shared.global [%0], [%1], 16, %2;"
                 :: "r"(dst), "l"(src), "r"(srcsize) : "memory");
}
#define CP_COMMIT() asm volatile("cp.async.commit_group;" ::: "memory")

__device__ __forceinline__ void ldmat_x4(uint32_t* r, uint32_t addr) {
    asm volatile("ldmatrix.sync.aligned.m8n8.x4.shared.b16 {%0,%1,%2,%3}, [%4];"
                 : "=r"(r[0]), "=r"(r[1]), "=r"(r[2]), "=r"(r[3]) : "r"(addr));
}
__device__ __forceinline__ void mma16816(float* c, const uint32_t* a, const uint32_t* b) {
    asm volatile("mma.sync.aligned.m16n8k16.row.col.f32.f16.f16.f32 "
                 "{%0,%1,%2,%3}, {%4,%5,%6,%7}, {%8,%9}, {%0,%1,%2,%3};"
                 : "+f"(c[0]), "+f"(c[1]), "+f"(c[2]), "+f"(c[3])
                 : "r"(a[0]), "r"(a[1]), "r"(a[2]), "r"(a[3]), "r"(b[0]), "r"(b[1]));
}

// ---------------- 1) NCHW fp32 -> NHWC fp16 transpose + row pooling ----------------
__global__ __launch_bounds__(256) void xT_kernel(const float* __restrict__ x) {
    __shared__ __half sA[8][64 * 33];
    __shared__ float sPool[128];
    int tid = threadIdx.x, w = tid >> 5, l = tid & 31;
    int by = blockIdx.x;              // b*128 + y
    int b = by >> 7, y = by & 127;
    int c0 = (w & 1) * 64, p0 = (w >> 1) * 32;
    if (tid < 128) sPool[tid] = 0.f;
    __syncthreads();
    __half* s = sA[w];
    #pragma unroll 8
    for (int i = 0; i < 64; i++) {
        float v = x[(((size_t)b * C_ + c0 + i) * H_ + y) * W_ + p0 + l];
        s[i * 33 + l] = __float2half_rn(v);
    }
    __syncwarp();
    // write phase: lane handles c-chunk c8=(l&7)*8, pixels (l>>3)+4i
    const int c8 = (l & 7) * 8;
    const int pxg = l >> 3;
    float pacc[8];
    #pragma unroll
    for (int j = 0; j < 8; j++) pacc[j] = 0.f;
    #pragma unroll
    for (int i = 0; i < 8; i++) {
        int pixl = pxg + 4 * i;
        uint32_t pk[4];
        #pragma unroll
        for (int j = 0; j < 4; j++) {
            __half h0 = s[(c8 + 2 * j) * 33 + pixl];
            __half h1 = s[(c8 + 2 * j + 1) * 33 + pixl];
            pacc[2 * j]     += __half2float(h0);
            pacc[2 * j + 1] += __half2float(h1);
            __half2 hv = __halves2half2(h0, h1);
            pk[j] = *(uint32_t*)&hv;
        }
        *(uint4*)(g_xT + (((size_t)b * H_ + y) * W_ + p0 + pixl) * C_ + c0 + c8) =
            make_uint4(pk[0], pk[1], pk[2], pk[3]);
    }
    #pragma unroll
    for (int j = 0; j < 8; j++) atomicAdd(&sPool[c0 + c8 + j], pacc[j]);
    __syncthreads();
    if (tid < 128)
        g_poolrow[((size_t)b * H_ + y) * C_ + tid] = sPool[tid];
}

// ---------------- 2) fused pooling finish + attention + agg_b ----------------
__global__ __launch_bounds__(128) void attn2_kernel(const float* __restrict__ w1,
                                                    const float* __restrict__ b1,
                                                    const float* __restrict__ w2,
                                                    const float* __restrict__ b2,
                                                    const float* __restrict__ bias) {
    __shared__ float sp[128];
    __shared__ float sh[K_];
    __shared__ float sa[K_];
    int b = blockIdx.x, tid = threadIdx.x, lane = tid & 31, wid = tid >> 5;

    float s = 0.f;
    const float* pr = g_poolrow + (size_t)b * H_ * C_ + tid;
    #pragma unroll 8
    for (int y = 0; y < H_; y++) s += pr[(size_t)y * C_];
    sp[tid] = s * (1.0f / (H_ * W_));
    __syncthreads();

    {   // warp wid computes h[wid]
        float p = 0.f;
        #pragma unroll
        for (int c = lane; c < C_; c += 32) p += sp[c] * w1[wid * C_ + c];
        #pragma unroll
        for (int off = 16; off > 0; off >>= 1) p += __shfl_down_sync(0xffffffffu, p, off);
        if (lane == 0) sh[wid] = fmaxf(p + b1[wid], 0.f);
    }
    __syncthreads();
    if (tid == 0) {
        float lg[K_];
        #pragma unroll
        for (int j = 0; j < K_; j++) {
            float t = b2[j];
            #pragma unroll
            for (int k = 0; k < K_; k++) t += sh[k] * w2[j * K_ + k];
            lg[j] = t;
        }
        float m = lg[0];
        #pragma unroll
        for (int j = 1; j < K_; j++) m = fmaxf(m, lg[j]);
        float den = 0.f, e[K_];
        #pragma unroll
        for (int j = 0; j < K_; j++) { e[j] = __expf(lg[j] - m); den += e[j]; }
        #pragma unroll
        for (int j = 0; j < K_; j++) {
            sa[j] = e[j] / den;
            g_attn[b * K_ + j] = sa[j];
        }
    }
    __syncthreads();
    float bb = 0.f;
    #pragma unroll
    for (int k = 0; k < K_; k++) bb += sa[k] * bias[k * O_ + tid];
    g_aggb[b * O_ + tid] = bb;
}

// ---------------- 3) weight aggregation -> fp16 [b][rs][o][c] ----------------
__global__ __launch_bounds__(256) void aggw16_kernel(const float* __restrict__ weight) {
    int idx = blockIdx.x * 256 + threadIdx.x;   // 16384 = O_*C_
    int b = blockIdx.y;
    int o = idx >> 7, c = idx & 127;
    float a0 = g_attn[b * K_ + 0], a1 = g_attn[b * K_ + 1];
    float a2 = g_attn[b * K_ + 2], a3 = g_attn[b * K_ + 3];
    const float* p0 = weight + ((size_t)(0 * O_ + o) * C_ + c) * RS_;
    const float* p1 = weight + ((size_t)(1 * O_ + o) * C_ + c) * RS_;
    const float* p2 = weight + ((size_t)(2 * O_ + o) * C_ + c) * RS_;
    const float* p3 = weight + ((size_t)(3 * O_ + o) * C_ + c) * RS_;
    #pragma unroll
    for (int rs = 0; rs < RS_; rs++) {
        float s = a0 * p0[rs] + a1 * p1[rs] + a2 * p2[rs] + a3 * p3[rs];
        g_aggw16[(((size_t)b * RS_ + rs) * O_ + o) * C_ + c] = __float2half_rn(s);
    }
}

// ---------------- 4) HMMA implicit-GEMM conv, 2 output rows / CTA ----------------
#define A_STRIDE 272
#define A_BYTES  (128 * A_STRIDE)            // 34816
#define SM_B_OFF (2 * A_BYTES)               // 69632
#define B_ROW    (130 * A_STRIDE)            // 35360
#define SMEM_CONV (SM_B_OFF + 4 * B_ROW)     // 211072

__global__ void __launch_bounds__(256, 1) conv_hmma(float* __restrict__ out) {
    extern __shared__ char smem[];
    const uint32_t sb = smem_u32(smem);
    const int tid = threadIdx.x, lane = tid & 31, wid = tid >> 5;
    const int b = blockIdx.y, y0 = blockIdx.x * 2;
    const int wm = wid & 1;
    const int wn = wid >> 1;                  // 0..3
    const int h  = wn >> 1;                   // 0/1 output row select
    const int nb = (wn & 1) * 64;             // pixel col base

    // ---- B staging: 4 input rows x 130 pixels x 128c fp16 (zfill halo) ----
    for (int i = tid; i < 8320; i += 256) {
        int rr = i / 2080, rem = i - rr * 2080;
        int p = rem >> 4, ch = rem & 15;
        int y = y0 - 1 + rr, px = p - 1;
        bool ok = (y >= 0) & (y < H_) & (px >= 0) & (px < W_);
        uint32_t dst = sb + SM_B_OFF + rr * B_ROW + p * A_STRIDE + ch * 16;
        const __half* src = g_xT + ((((size_t)b * H_ + (ok ? y : 0)) * W_ + (ok ? px : 0)) * C_ + ch * 8);
        cp16(dst, src, ok ? 16 : 0);
    }
    {
        const __half* asrc = g_aggw16 + ((size_t)b * RS_ + 0) * O_ * C_;
        for (int i = tid; i < 2048; i += 256) {
            int o = i >> 4, ch = i & 15;
            cp16(sb + o * A_STRIDE + ch * 16, asrc + (size_t)o * C_ + ch * 8, 16);
        }
    }
    CP_COMMIT();
    {
        const __half* asrc = g_aggw16 + ((size_t)b * RS_ + 1) * O_ * C_;
        for (int i = tid; i < 2048; i += 256) {
            int o = i >> 4, ch = i & 15;
            cp16(sb + A_BYTES + o * A_STRIDE + ch * 16, asrc + (size_t)o * C_ + ch * 8, 16);
        }
    }
    CP_COMMIT();

    float acc[4][8][4];
    #pragma unroll
    for (int mt = 0; mt < 4; mt++)
        #pragma unroll
        for (int nt = 0; nt < 8; nt++)
            #pragma unroll
            for (int j = 0; j < 4; j++) acc[mt][nt][j] = 0.f;

    const int lAr = lane & 15;
    const int lAk = (lane >> 4) * 16;
    const int lg  = lane >> 3;
    const int lr  = lane & 7;
    const int lBrow = (lg >> 1) * 8 + lr;
    const int lBk   = (lg & 1) * 16;

    for (int rs = 0; rs < 9; rs++) {
        if (rs < 8) asm volatile("cp.async.wait_group 1;" ::: "memory");
        else        asm volatile("cp.async.wait_group 0;" ::: "memory");
        __syncthreads();

        const uint32_t Ab = sb + (rs & 1) * A_BYTES;
        const int r = rs / 3, s = rs - 3 * r;
        const uint32_t Bbase = sb + SM_B_OFF + (r + h) * B_ROW
                             + (nb + lBrow + s) * A_STRIDE + lBk;
        const uint32_t Abase = Ab + (wm * 64 + lAr) * A_STRIDE + lAk;

        // fragment double buffers
        uint32_t bf[2][8][2];
        uint32_t af[2][4];
        #pragma unroll
        for (int nt2 = 0; nt2 < 4; nt2++) {
            uint32_t t[4];
            ldmat_x4(t, Bbase + nt2 * (16 * A_STRIDE));
            bf[0][2 * nt2][0] = t[0]; bf[0][2 * nt2][1] = t[1];
            bf[0][2 * nt2 + 1][0] = t[2]; bf[0][2 * nt2 + 1][1] = t[3];
        }
        ldmat_x4(af[0], Abase);

        #pragma unroll
        for (int kc = 0; kc < 8; kc++) {
            // prefetch B frags for kc+1
            if (kc < 7) {
                #pragma unroll
                for (int nt2 = 0; nt2 < 4; nt2++) {
                    uint32_t t[4];
                    ldmat_x4(t, Bbase + nt2 * (16 * A_STRIDE) + (kc + 1) * 32);
                    bf[(kc + 1) & 1][2 * nt2][0] = t[0]; bf[(kc + 1) & 1][2 * nt2][1] = t[1];
                    bf[(kc + 1) & 1][2 * nt2 + 1][0] = t[2]; bf[(kc + 1) & 1][2 * nt2 + 1][1] = t[3];
                }
            }
            #pragma unroll
            for (int mt = 0; mt < 4; mt++) {
                // prefetch A frag for next (mt,kc) step
                int nmt = (mt + 1) & 3;
                int nkc = (mt == 3) ? kc + 1 : kc;
                if (nkc < 8)
                    ldmat_x4(af[(mt + 1) & 1], Abase + nmt * 16 * A_STRIDE + nkc * 32);
                #pragma unroll
                for (int nt = 0; nt < 8; nt++)
                    mma16816(acc[mt][nt], af[mt & 1], bf[kc & 1][nt]);
            }
        }
        __syncthreads();
        if (rs + 2 < 9) {
            const __half* asrc = g_aggw16 + ((size_t)b * RS_ + rs + 2) * O_ * C_;
            uint32_t dbuf = sb + (rs & 1) * A_BYTES;
            for (int i = tid; i < 2048; i += 256) {
                int o = i >> 4, ch = i & 15;
                cp16(dbuf + o * A_STRIDE + ch * 16, asrc + (size_t)o * C_ + ch * 8, 16);
            }
            CP_COMMIT();
        }
    }

    // ---- epilogue: bias + stores ----
    const int g = lane >> 2, t4 = lane & 3;
    const int yout = y0 + h;
    #pragma unroll
    for (int mt = 0; mt < 4; mt++) {
        int o_lo = wm * 64 + mt * 16 + g;
        float b_lo = g_aggb[b * O_ + o_lo];
        float b_hi = g_aggb[b * O_ + o_lo + 8];
        float* p_lo = out + ((size_t)(b * O_ + o_lo) * H_ + yout) * W_;
        float* p_hi = p_lo + (size_t)8 * H_ * W_;
        #pragma unroll
        for (int nt = 0; nt < 8; nt++) {
            int xp = nb + nt * 8 + t4 * 2;
            float2 vlo = make_float2(acc[mt][nt][0] + b_lo, acc[mt][nt][1] + b_lo);
            float2 vhi = make_float2(acc[mt][nt][2] + b_hi, acc[mt][nt][3] + b_hi);
            *(float2*)(p_lo + xp) = vlo;
            *(float2*)(p_hi + xp) = vhi;
        }
    }
}

// ---------------- launch ----------------
extern "C" void kernel_launch(void* const* d_in, const int* in_sizes, int n_in,
                              void* d_out, int out_size) {
    const float* x      = (const float*)d_in[0];
    const float* att_w1 = (const float*)d_in[1];
    const float* att_b1 = (const float*)d_in[2];
    const float* att_w2 = (const float*)d_in[3];
    const float* att_b2 = (const float*)d_in[4];
    const float* weight = (const float*)d_in[5];
    const float* bias   = (const float*)d_in[6];
    float* out = (float*)d_out;

    cudaFuncSetAttribute(conv_hmma, cudaFuncAttributeMaxDynamicSharedMemorySize, SMEM_CONV);

    xT_kernel<<<B_ * H_, 256>>>(x);
    attn2_kernel<<<B_, 128>>>(att_w1, att_b1, att_w2, att_b2, bias);
    aggw16_kernel<<<dim3(64, B_), 256>>>(weight);
    conv_hmma<<<dim3(H_ / 2, B_), 256, SMEM_CONV>>>(out);
}

// round 6
// speedup vs baseline: 6.6164x; 1.0149x over previous
#include <cuda_runtime.h>
#include <cuda_fp16.h>
#include <cstdint>

#define B_ 32
#define C_ 128
#define H_ 128
#define W_ 128
#define K_ 4
#define O_ 128
#define RS_ 9
#define NCTA 152
#define TILES (B_ * H_)

// ---------------- scratch ----------------
__device__ float  g_poolrow[(size_t)B_ * H_ * C_];
__device__ float  g_attn[B_ * K_];
__device__ float  g_aggb[B_ * O_];
__device__ __half g_aggw16[(size_t)B_ * RS_ * O_ * C_];      // [b][rs][o][c]
__device__ __half g_xT[(size_t)B_ * H_ * W_ * C_];           // [b][y][p][c] NHWC fp16

// ---------------- helpers ----------------
__device__ __forceinline__ uint32_t smem_u32(const void* p) {
    uint32_t a;
    asm("{ .reg .u64 t; cvta.to.shared.u64 t, %1; cvt.u32.u64 %0, t; }" : "=r"(a) : "l"(p));
    return a;
}
__device__ __forceinline__ void cp16(uint32_t dst, const void* src, int srcsize) {
    asm volatile("cp.async.cg.shared.global [%0], [%1], 16, %2;"
                 :: "r"(dst), "l"(src), "r"(srcsize) : "memory");
}
#define CP_COMMIT() asm volatile("cp.async.commit_group;" ::: "memory")
#define CP_WAIT(n)  asm volatile("cp.async.wait_group %0;" :: "n"(n) : "memory")

__device__ __forceinline__ void ldmat_x4(uint32_t* r, uint32_t addr) {
    asm volatile("ldmatrix.sync.aligned.m8n8.x4.shared.b16 {%0,%1,%2,%3}, [%4];"
                 : "=r"(r[0]), "=r"(r[1]), "=r"(r[2]), "=r"(r[3]) : "r"(addr));
}
__device__ __forceinline__ void mma16816(float* c, const uint32_t* a, const uint32_t* b) {
    asm volatile("mma.sync.aligned.m16n8k16.row.col.f32.f16.f16.f32 "
                 "{%0,%1,%2,%3}, {%4,%5,%6,%7}, {%8,%9}, {%0,%1,%2,%3};"
                 : "+f"(c[0]), "+f"(c[1]), "+f"(c[2]), "+f"(c[3])
                 : "r"(a[0]), "r"(a[1]), "r"(a[2]), "r"(a[3]), "r"(b[0]), "r"(b[1]));
}

// ---------------- 1) NCHW fp32 -> NHWC fp16 transpose + row pooling ----------------
__global__ __launch_bounds__(256) void xT_kernel(const float* __restrict__ x) {
    __shared__ __half sA[8][64 * 33];
    __shared__ float sPool[128];
    int tid = threadIdx.x, w = tid >> 5, l = tid & 31;
    int by = blockIdx.x;
    int b = by >> 7, y = by & 127;
    int c0 = (w & 1) * 64, p0 = (w >> 1) * 32;
    if (tid < 128) sPool[tid] = 0.f;
    __syncthreads();
    __half* s = sA[w];
    #pragma unroll 8
    for (int i = 0; i < 64; i++) {
        float v = x[(((size_t)b * C_ + c0 + i) * H_ + y) * W_ + p0 + l];
        s[i * 33 + l] = __float2half_rn(v);
    }
    __syncwarp();
    const int c8 = (l & 7) * 8;
    const int pxg = l >> 3;
    float pacc[8];
    #pragma unroll
    for (int j = 0; j < 8; j++) pacc[j] = 0.f;
    #pragma unroll
    for (int i = 0; i < 8; i++) {
        int pixl = pxg + 4 * i;
        uint32_t pk[4];
        #pragma unroll
        for (int j = 0; j < 4; j++) {
            __half h0 = s[(c8 + 2 * j) * 33 + pixl];
            __half h1 = s[(c8 + 2 * j + 1) * 33 + pixl];
            pacc[2 * j]     += __half2float(h0);
            pacc[2 * j + 1] += __half2float(h1);
            __half2 hv = __halves2half2(h0, h1);
            pk[j] = *(uint32_t*)&hv;
        }
        *(uint4*)(g_xT + (((size_t)b * H_ + y) * W_ + p0 + pixl) * C_ + c0 + c8) =
            make_uint4(pk[0], pk[1], pk[2], pk[3]);
    }
    #pragma unroll
    for (int j = 0; j < 8; j++) atomicAdd(&sPool[c0 + c8 + j], pacc[j]);
    __syncthreads();
    if (tid < 128)
        g_poolrow[((size_t)b * H_ + y) * C_ + tid] = sPool[tid];
}

// ---------------- 2) fused pooling finish + attention + agg_b ----------------
__global__ __launch_bounds__(128) void attn2_kernel(const float* __restrict__ w1,
                                                    const float* __restrict__ b1,
                                                    const float* __restrict__ w2,
                                                    const float* __restrict__ b2,
                                                    const float* __restrict__ bias) {
    __shared__ float sp[128];
    __shared__ float sh[K_];
    __shared__ float sa[K_];
    int b = blockIdx.x, tid = threadIdx.x, lane = tid & 31, wid = tid >> 5;

    float s = 0.f;
    const float* pr = g_poolrow + (size_t)b * H_ * C_ + tid;
    #pragma unroll 8
    for (int y = 0; y < H_; y++) s += pr[(size_t)y * C_];
    sp[tid] = s * (1.0f / (H_ * W_));
    __syncthreads();

    {
        float p = 0.f;
        #pragma unroll
        for (int c = lane; c < C_; c += 32) p += sp[c] * w1[wid * C_ + c];
        #pragma unroll
        for (int off = 16; off > 0; off >>= 1) p += __shfl_down_sync(0xffffffffu, p, off);
        if (lane == 0) sh[wid] = fmaxf(p + b1[wid], 0.f);
    }
    __syncthreads();
    if (tid == 0) {
        float lg[K_];
        #pragma unroll
        for (int j = 0; j < K_; j++) {
            float t = b2[j];
            #pragma unroll
            for (int k = 0; k < K_; k++) t += sh[k] * w2[j * K_ + k];
            lg[j] = t;
        }
        float m = lg[0];
        #pragma unroll
        for (int j = 1; j < K_; j++) m = fmaxf(m, lg[j]);
        float den = 0.f, e[K_];
        #pragma unroll
        for (int j = 0; j < K_; j++) { e[j] = __expf(lg[j] - m); den += e[j]; }
        #pragma unroll
        for (int j = 0; j < K_; j++) {
            sa[j] = e[j] / den;
            g_attn[b * K_ + j] = sa[j];
        }
    }
    __syncthreads();
    float bb = 0.f;
    #pragma unroll
    for (int k = 0; k < K_; k++) bb += sa[k] * bias[k * O_ + tid];
    g_aggb[b * O_ + tid] = bb;
}

// ---------------- 3) weight aggregation -> fp16 [b][rs][o][c] ----------------
__global__ __launch_bounds__(256) void aggw16_kernel(const float* __restrict__ weight) {
    int idx = blockIdx.x * 256 + threadIdx.x;
    int b = blockIdx.y;
    int o = idx >> 7, c = idx & 127;
    float a0 = g_attn[b * K_ + 0], a1 = g_attn[b * K_ + 1];
    float a2 = g_attn[b * K_ + 2], a3 = g_attn[b * K_ + 3];
    const float* p0 = weight + ((size_t)(0 * O_ + o) * C_ + c) * RS_;
    const float* p1 = weight + ((size_t)(1 * O_ + o) * C_ + c) * RS_;
    const float* p2 = weight + ((size_t)(2 * O_ + o) * C_ + c) * RS_;
    const float* p3 = weight + ((size_t)(3 * O_ + o) * C_ + c) * RS_;
    #pragma unroll
    for (int rs = 0; rs < RS_; rs++) {
        float s = a0 * p0[rs] + a1 * p1[rs] + a2 * p2[rs] + a3 * p3[rs];
        g_aggw16[(((size_t)b * RS_ + rs) * O_ + o) * C_ + c] = __float2half_rn(s);
    }
}

// ---------------- 4) persistent HMMA implicit-GEMM conv ----------------
// 152 persistent CTAs; tile = (b, y): 128o x 128pix x K=1152.
// B ring: 4 row slots keyed by (row+4)&3; A double buffer with per-tile parity flip.
#define A_STRIDE 272
#define A_BYTES  (128 * A_STRIDE)            // 34816
#define SM_B_OFF (2 * A_BYTES)               // 69632
#define B_ROW    (130 * A_STRIDE)            // 35360
#define SMEM_CONV (SM_B_OFF + 4 * B_ROW)     // 211072

__device__ __forceinline__ void stage_A(uint32_t sb, int buf, const __half* __restrict__ asrc,
                                        int tid) {
    uint32_t dst = sb + buf * A_BYTES;
    #pragma unroll
    for (int k = 0; k < 8; k++) {
        int i = tid + k * 256;
        int o = i >> 4, ch = i & 15;
        cp16(dst + o * A_STRIDE + ch * 16, asrc + (size_t)o * C_ + ch * 8, 16);
    }
}
__device__ __forceinline__ void stage_Brow(uint32_t sb, int b, int ry, int tid) {
    int slot = (ry + 4) & 3;
    bool rok = (ry >= 0) & (ry < H_);
    const __half* rbase = g_xT + ((size_t)b * H_ + (rok ? ry : 0)) * W_ * C_;
    uint32_t dst = sb + SM_B_OFF + slot * B_ROW;
    for (int i = tid; i < 2080; i += 256) {
        int p = i >> 4, ch = i & 15;
        int px = p - 1;
        bool ok = rok & (px >= 0) & (px < W_);
        cp16(dst + p * A_STRIDE + ch * 16, rbase + (size_t)(ok ? px : 0) * C_ + ch * 8,
             ok ? 16 : 0);
    }
}

__global__ void __launch_bounds__(256, 1) conv_hmma(float* __restrict__ out) {
    extern __shared__ char smem[];
    const uint32_t sb = smem_u32(smem);
    const int tid = threadIdx.x, lane = tid & 31, wid = tid >> 5;
    const int wm = wid & 1;                    // o half
    const int nb = (wid >> 1) * 32;            // pixel quarter

    const int lAr = lane & 15;
    const int lAk = (lane >> 4) * 16;
    const int lg  = lane >> 3;
    const int lr  = lane & 7;
    const int lBrow = (lg >> 1) * 8 + lr;
    const int lBk   = (lg & 1) * 16;

    // chunk assignment: base=TILES/NCTA, first rem CTAs get one extra
    const int cbase = TILES / NCTA;
    const int crem  = TILES % NCTA;
    const int cid   = blockIdx.x;
    const int cnt   = cbase + (cid < crem ? 1 : 0);
    const int start = cid * cbase + (cid < crem ? cid : crem);
    if (cnt == 0) return;

    int apar = 0;

    for (int t = start; t < start + cnt; t++) {
        const int b = t >> 7, y = t & 127;
        const bool cold = (t == start) || (y == 0);

        if (cold) {
            CP_WAIT(0);
            __syncthreads();
            apar = 0;
            stage_Brow(sb, b, y - 1, tid);
            stage_Brow(sb, b, y,     tid);
            stage_Brow(sb, b, y + 1, tid);
            stage_A(sb, 0, g_aggw16 + ((size_t)b * RS_ + 0) * O_ * C_, tid);
            CP_COMMIT();
            stage_A(sb, 1, g_aggw16 + ((size_t)b * RS_ + 1) * O_ * C_, tid);
            CP_COMMIT();
        }

        float acc[4][4][4];
        #pragma unroll
        for (int mt = 0; mt < 4; mt++)
            #pragma unroll
            for (int nt = 0; nt < 4; nt++)
                #pragma unroll
                for (int j = 0; j < 4; j++) acc[mt][nt][j] = 0.f;

        for (int rs = 0; rs < 9; rs++) {
            CP_WAIT(1);
            __syncthreads();

            const int abuf = (rs + apar) & 1;
            const int r = rs / 3, s = rs - 3 * r;
            const int ry = y - 1 + r;
            const uint32_t Bbase = sb + SM_B_OFF + (uint32_t)((ry + 4) & 3) * B_ROW
                                 + (nb + lBrow + s) * A_STRIDE + lBk;
            const uint32_t Abase = sb + abuf * A_BYTES + (wm * 64 + lAr) * A_STRIDE + lAk;

            uint32_t bf[2][4][2];
            uint32_t af[2][4];
            {
                uint32_t tt[4];
                ldmat_x4(tt, Bbase);
                bf[0][0][0] = tt[0]; bf[0][0][1] = tt[1];
                bf[0][1][0] = tt[2]; bf[0][1][1] = tt[3];
                ldmat_x4(tt, Bbase + 16 * A_STRIDE);
                bf[0][2][0] = tt[0]; bf[0][2][1] = tt[1];
                bf[0][3][0] = tt[2]; bf[0][3][1] = tt[3];
            }
            ldmat_x4(af[0], Abase);

            #pragma unroll
            for (int kc = 0; kc < 8; kc++) {
                if (kc < 7) {
                    uint32_t tt[4];
                    ldmat_x4(tt, Bbase + (kc + 1) * 32);
                    bf[(kc + 1) & 1][0][0] = tt[0]; bf[(kc + 1) & 1][0][1] = tt[1];
                    bf[(kc + 1) & 1][1][0] = tt[2]; bf[(kc + 1) & 1][1][1] = tt[3];
                    ldmat_x4(tt, Bbase + 16 * A_STRIDE + (kc + 1) * 32);
                    bf[(kc + 1) & 1][2][0] = tt[0]; bf[(kc + 1) & 1][2][1] = tt[1];
                    bf[(kc + 1) & 1][3][0] = tt[2]; bf[(kc + 1) & 1][3][1] = tt[3];
                }
                #pragma unroll
                for (int mt = 0; mt < 4; mt++) {
                    int nmt = (mt + 1) & 3;
                    int nkc = (mt == 3) ? kc + 1 : kc;
                    if (nkc < 8)
                        ldmat_x4(af[(mt + 1) & 1], Abase + nmt * 16 * A_STRIDE + nkc * 32);
                    #pragma unroll
                    for (int nt = 0; nt < 4; nt++)
                        mma16816(acc[mt][nt], af[mt & 1], bf[kc & 1][nt]);
                }
            }
            __syncthreads();

            // next stage: A((rs+2)%9), plus B row y+2 rides the rs==0 group
            {
                int nrs = rs + 2;
                int crs = (nrs < 9) ? nrs : nrs - 9;
                stage_A(sb, (rs + apar) & 1,
                        g_aggw16 + ((size_t)b * RS_ + crs) * O_ * C_, tid);
                if (rs == 0) stage_Brow(sb, b, y + 2, tid);
                CP_COMMIT();
            }
        }
        apar ^= 1;

        // ---- epilogue ----
        const int g = lane >> 2, t4 = lane & 3;
        #pragma unroll
        for (int mt = 0; mt < 4; mt++) {
            int o_lo = wm * 64 + mt * 16 + g;
            float b_lo = g_aggb[b * O_ + o_lo];
            float b_hi = g_aggb[b * O_ + o_lo + 8];
            float* p_lo = out + ((size_t)(b * O_ + o_lo) * H_ + y) * W_;
            float* p_hi = p_lo + (size_t)8 * H_ * W_;
            #pragma unroll
            for (int nt = 0; nt < 4; nt++) {
                int xp = nb + nt * 8 + t4 * 2;
                float2 vlo = make_float2(acc[mt][nt][0] + b_lo, acc[mt][nt][1] + b_lo);
                float2 vhi = make_float2(acc[mt][nt][2] + b_hi, acc[mt][nt][3] + b_hi);
                *(float2*)(p_lo + xp) = vlo;
                *(float2*)(p_hi + xp) = vhi;
            }
        }
    }
    CP_WAIT(0);
}

// ---------------- launch ----------------
extern "C" void kernel_launch(void* const* d_in, const int* in_sizes, int n_in,
                              void* d_out, int out_size) {
    const float* x      = (const float*)d_in[0];
    const float* att_w1 = (const float*)d_in[1];
    const float* att_b1 = (const float*)d_in[2];
    const float* att_w2 = (const float*)d_in[3];
    const float* att_b2 = (const float*)d_in[4];
    const float* weight = (const float*)d_in[5];
    const float* bias   = (const float*)d_in[6];
    float* out = (float*)d_out;

    cudaFuncSetAttribute(conv_hmma, cudaFuncAttributeMaxDynamicSharedMemorySize, SMEM_CONV);

    xT_kernel<<<B_ * H_, 256>>>(x);
    attn2_kernel<<<B_, 128>>>(att_w1, att_b1, att_w2, att_b2, bias);
    aggw16_kernel<<<dim3(64, B_), 256>>>(weight);
    conv_hmma<<<NCTA, 256, SMEM_CONV>>>(out);
}

// round 7
// speedup vs baseline: 7.1368x; 1.0787x over previous
#include <cuda_runtime.h>
#include <cuda_fp16.h>
#include <cstdint>

#define B_ 32
#define C_ 128
#define H_ 128
#define W_ 128
#define K_ 4
#define O_ 128
#define RS_ 9
#define NCTA 152
#define TILES2 (B_ * (H_ / 2))   // 2048 two-row tiles

// ---------------- scratch ----------------
__device__ float  g_poolrow[(size_t)B_ * H_ * C_];
__device__ float  g_attn[B_ * K_];
__device__ float  g_aggb[B_ * O_];
__device__ __half g_aggw16[(size_t)B_ * RS_ * O_ * C_];      // [b][rs][o][c]
__device__ __half g_xT[(size_t)B_ * H_ * W_ * C_];           // [b][y][p][c] NHWC fp16

// ---------------- helpers ----------------
__device__ __forceinline__ uint32_t smem_u32(const void* p) {
    uint32_t a;
    asm("{ .reg .u64 t; cvta.to.shared.u64 t, %1; cvt.u32.u64 %0, t; }" : "=r"(a) : "l"(p));
    return a;
}
__device__ __forceinline__ void cp16(uint32_t dst, const void* src, int srcsize) {
    asm volatile("cp.async.cg.shared.global [%0], [%1], 16, %2;"
                 :: "r"(dst), "l"(src), "r"(srcsize) : "memory");
}
#define CP_COMMIT() asm volatile("cp.async.commit_group;" ::: "memory")
#define CP_WAIT(n)  asm volatile("cp.async.wait_group %0;" :: "n"(n) : "memory")

__device__ __forceinline__ void ldmat_x4(uint32_t* r, uint32_t addr) {
    asm volatile("ldmatrix.sync.aligned.m8n8.x4.shared.b16 {%0,%1,%2,%3}, [%4];"
                 : "=r"(r[0]), "=r"(r[1]), "=r"(r[2]), "=r"(r[3]) : "r"(addr));
}
__device__ __forceinline__ void mma16816(float* c, const uint32_t* a, const uint32_t* b) {
    asm volatile("mma.sync.aligned.m16n8k16.row.col.f32.f16.f16.f32 "
                 "{%0,%1,%2,%3}, {%4,%5,%6,%7}, {%8,%9}, {%0,%1,%2,%3};"
                 : "+f"(c[0]), "+f"(c[1]), "+f"(c[2]), "+f"(c[3])
                 : "r"(a[0]), "r"(a[1]), "r"(a[2]), "r"(a[3]), "r"(b[0]), "r"(b[1]));
}

// ---------------- 1) NCHW fp32 -> NHWC fp16 transpose + row pooling ----------------
__global__ __launch_bounds__(256) void xT_kernel(const float* __restrict__ x) {
    __shared__ __half sA[8][64 * 33];
    __shared__ float sPool[128];
    int tid = threadIdx.x, w = tid >> 5, l = tid & 31;
    int by = blockIdx.x;
    int b = by >> 7, y = by & 127;
    int c0 = (w & 1) * 64, p0 = (w >> 1) * 32;
    if (tid < 128) sPool[tid] = 0.f;
    __syncthreads();
    __half* s = sA[w];
    #pragma unroll 8
    for (int i = 0; i < 64; i++) {
        float v = x[(((size_t)b * C_ + c0 + i) * H_ + y) * W_ + p0 + l];
        s[i * 33 + l] = __float2half_rn(v);
    }
    __syncwarp();
    const int c8 = (l & 7) * 8;
    const int pxg = l >> 3;
    float pacc[8];
    #pragma unroll
    for (int j = 0; j < 8; j++) pacc[j] = 0.f;
    #pragma unroll
    for (int i = 0; i < 8; i++) {
        int pixl = pxg + 4 * i;
        uint32_t pk[4];
        #pragma unroll
        for (int j = 0; j < 4; j++) {
            __half h0 = s[(c8 + 2 * j) * 33 + pixl];
            __half h1 = s[(c8 + 2 * j + 1) * 33 + pixl];
            pacc[2 * j]     += __half2float(h0);
            pacc[2 * j + 1] += __half2float(h1);
            __half2 hv = __halves2half2(h0, h1);
            pk[j] = *(uint32_t*)&hv;
        }
        *(uint4*)(g_xT + (((size_t)b * H_ + y) * W_ + p0 + pixl) * C_ + c0 + c8) =
            make_uint4(pk[0], pk[1], pk[2], pk[3]);
    }
    #pragma unroll
    for (int j = 0; j < 8; j++) atomicAdd(&sPool[c0 + c8 + j], pacc[j]);
    __syncthreads();
    if (tid < 128)
        g_poolrow[((size_t)b * H_ + y) * C_ + tid] = sPool[tid];
}

// ---------------- 2) fused pooling finish + attention + agg_b ----------------
__global__ __launch_bounds__(128) void attn2_kernel(const float* __restrict__ w1,
                                                    const float* __restrict__ b1,
                                                    const float* __restrict__ w2,
                                                    const float* __restrict__ b2,
                                                    const float* __restrict__ bias) {
    __shared__ float sp[128];
    __shared__ float sh[K_];
    __shared__ float sa[K_];
    int b = blockIdx.x, tid = threadIdx.x, lane = tid & 31, wid = tid >> 5;

    float s = 0.f;
    const float* pr = g_poolrow + (size_t)b * H_ * C_ + tid;
    #pragma unroll 8
    for (int y = 0; y < H_; y++) s += pr[(size_t)y * C_];
    sp[tid] = s * (1.0f / (H_ * W_));
    __syncthreads();

    {
        float p = 0.f;
        #pragma unroll
        for (int c = lane; c < C_; c += 32) p += sp[c] * w1[wid * C_ + c];
        #pragma unroll
        for (int off = 16; off > 0; off >>= 1) p += __shfl_down_sync(0xffffffffu, p, off);
        if (lane == 0) sh[wid] = fmaxf(p + b1[wid], 0.f);
    }
    __syncthreads();
    if (tid == 0) {
        float lg[K_];
        #pragma unroll
        for (int j = 0; j < K_; j++) {
            float t = b2[j];
            #pragma unroll
            for (int k = 0; k < K_; k++) t += sh[k] * w2[j * K_ + k];
            lg[j] = t;
        }
        float m = lg[0];
        #pragma unroll
        for (int j = 1; j < K_; j++) m = fmaxf(m, lg[j]);
        float den = 0.f, e[K_];
        #pragma unroll
        for (int j = 0; j < K_; j++) { e[j] = __expf(lg[j] - m); den += e[j]; }
        #pragma unroll
        for (int j = 0; j < K_; j++) {
            sa[j] = e[j] / den;
            g_attn[b * K_ + j] = sa[j];
        }
    }
    __syncthreads();
    float bb = 0.f;
    #pragma unroll
    for (int k = 0; k < K_; k++) bb += sa[k] * bias[k * O_ + tid];
    g_aggb[b * O_ + tid] = bb;
}

// ---------------- 3) weight aggregation -> fp16 [b][rs][o][c] ----------------
__global__ __launch_bounds__(256) void aggw16_kernel(const float* __restrict__ weight) {
    int idx = blockIdx.x * 256 + threadIdx.x;
    int b = blockIdx.y;
    int o = idx >> 7, c = idx & 127;
    float a0 = g_attn[b * K_ + 0], a1 = g_attn[b * K_ + 1];
    float a2 = g_attn[b * K_ + 2], a3 = g_attn[b * K_ + 3];
    const float* p0 = weight + ((size_t)(0 * O_ + o) * C_ + c) * RS_;
    const float* p1 = weight + ((size_t)(1 * O_ + o) * C_ + c) * RS_;
    const float* p2 = weight + ((size_t)(2 * O_ + o) * C_ + c) * RS_;
    const float* p3 = weight + ((size_t)(3 * O_ + o) * C_ + c) * RS_;
    #pragma unroll
    for (int rs = 0; rs < RS_; rs++) {
        float s = a0 * p0[rs] + a1 * p1[rs] + a2 * p2[rs] + a3 * p3[rs];
        g_aggw16[(((size_t)b * RS_ + rs) * O_ + o) * C_ + c] = __float2half_rn(s);
    }
}

// ---------------- 4) persistent HMMA conv: 512 threads, 2-row tiles ----------------
#define A_STRIDE 272
#define A_BYTES  (128 * A_STRIDE)            // 34816
#define SM_B_OFF (2 * A_BYTES)               // 69632
#define B_ROW    (130 * A_STRIDE)            // 35360
#define SMEM_CONV (SM_B_OFF + 4 * B_ROW)     // 211072

__device__ __forceinline__ void stage_A(uint32_t sb, int buf, const __half* __restrict__ asrc,
                                        int tid) {
    uint32_t dst = sb + buf * A_BYTES;
    #pragma unroll
    for (int k = 0; k < 4; k++) {
        int i = tid + k * 512;
        int o = i >> 4, ch = i & 15;
        cp16(dst + o * A_STRIDE + ch * 16, asrc + (size_t)o * C_ + ch * 8, 16);
    }
}
__device__ __forceinline__ void stage_Brow(uint32_t sb, int b, int ry, int tid) {
    int slot = (ry + 4) & 3;
    bool rok = (ry >= 0) & (ry < H_);
    const __half* rbase = g_xT + ((size_t)b * H_ + (rok ? ry : 0)) * W_ * C_;
    uint32_t dst = sb + SM_B_OFF + slot * B_ROW;
    for (int i = tid; i < 2080; i += 512) {
        int p = i >> 4, ch = i & 15;
        int px = p - 1;
        bool ok = rok & (px >= 0) & (px < W_);
        cp16(dst + p * A_STRIDE + ch * 16, rbase + (size_t)(ok ? px : 0) * C_ + ch * 8,
             ok ? 16 : 0);
    }
}

__global__ void __launch_bounds__(512, 1) conv_hmma(float* __restrict__ out) {
    extern __shared__ char smem[];
    const uint32_t sb = smem_u32(smem);
    const int tid = threadIdx.x, lane = tid & 31, wid = tid >> 5;   // 16 warps
    const int wm = wid & 1;                    // o half (0/64)
    const int wq = wid >> 1;                   // 0..7
    const int h  = wq >> 2;                    // output row within pair
    const int nb = (wq & 3) * 32;              // pixel quarter

    const int lAr = lane & 15;
    const int lAk = (lane >> 4) * 16;
    const int lg  = lane >> 3;
    const int lr  = lane & 7;
    const int lBrow = (lg >> 1) * 8 + lr;
    const int lBk   = (lg & 1) * 16;

    const int cbase = TILES2 / NCTA;
    const int crem  = TILES2 % NCTA;
    const int cid   = blockIdx.x;
    const int cnt   = cbase + (cid < crem ? 1 : 0);
    const int start = cid * cbase + (cid < crem ? cid : crem);
    if (cnt == 0) return;

    int apar = 0;

    for (int t = start; t < start + cnt; t++) {
        const int b = t >> 6, yp = t & 63, y0 = yp * 2;
        const bool cold = (t == start) || (yp == 0);

        if (cold) {
            CP_WAIT(0);
            __syncthreads();
            apar = 0;
            stage_Brow(sb, b, y0 - 1, tid);
            stage_Brow(sb, b, y0,     tid);
            stage_Brow(sb, b, y0 + 1, tid);
            stage_Brow(sb, b, y0 + 2, tid);
            stage_A(sb, 0, g_aggw16 + ((size_t)b * RS_ + 0) * O_ * C_, tid);
            CP_COMMIT();
            stage_A(sb, 1, g_aggw16 + ((size_t)b * RS_ + 1) * O_ * C_, tid);
            CP_COMMIT();
        }

        float acc[4][4][4];
        #pragma unroll
        for (int mt = 0; mt < 4; mt++)
            #pragma unroll
            for (int nt = 0; nt < 4; nt++)
                #pragma unroll
                for (int j = 0; j < 4; j++) acc[mt][nt][j] = 0.f;

        for (int rs = 0; rs < 9; rs++) {
            CP_WAIT(1);
            __syncthreads();

            const int abuf = (rs + apar) & 1;
            const int r = rs / 3, s = rs - 3 * r;
            const int ry = y0 - 1 + r + h;
            const uint32_t Bbase = sb + SM_B_OFF + (uint32_t)((ry + 4) & 3) * B_ROW
                                 + (nb + lBrow + s) * A_STRIDE + lBk;
            const uint32_t Abase = sb + abuf * A_BYTES + (wm * 64 + lAr) * A_STRIDE + lAk;

            uint32_t bf[2][4][2];
            uint32_t af[2][4];
            {
                uint32_t tt[4];
                ldmat_x4(tt, Bbase);
                bf[0][0][0] = tt[0]; bf[0][0][1] = tt[1];
                bf[0][1][0] = tt[2]; bf[0][1][1] = tt[3];
                ldmat_x4(tt, Bbase + 16 * A_STRIDE);
                bf[0][2][0] = tt[0]; bf[0][2][1] = tt[1];
                bf[0][3][0] = tt[2]; bf[0][3][1] = tt[3];
            }
            ldmat_x4(af[0], Abase);

            #pragma unroll
            for (int kc = 0; kc < 8; kc++) {
                if (kc < 7) {
                    uint32_t tt[4];
                    ldmat_x4(tt, Bbase + (kc + 1) * 32);
                    bf[(kc + 1) & 1][0][0] = tt[0]; bf[(kc + 1) & 1][0][1] = tt[1];
                    bf[(kc + 1) & 1][1][0] = tt[2]; bf[(kc + 1) & 1][1][1] = tt[3];
                    ldmat_x4(tt, Bbase + 16 * A_STRIDE + (kc + 1) * 32);
                    bf[(kc + 1) & 1][2][0] = tt[0]; bf[(kc + 1) & 1][2][1] = tt[1];
                    bf[(kc + 1) & 1][3][0] = tt[2]; bf[(kc + 1) & 1][3][1] = tt[3];
                }
                #pragma unroll
                for (int mt = 0; mt < 4; mt++) {
                    int nmt = (mt + 1) & 3;
                    int nkc = (mt == 3) ? kc + 1 : kc;
                    if (nkc < 8)
                        ldmat_x4(af[(mt + 1) & 1], Abase + nmt * 16 * A_STRIDE + nkc * 32);
                    #pragma unroll
                    for (int nt = 0; nt < 4; nt++)
                        mma16816(acc[mt][nt], af[mt & 1], bf[kc & 1][nt]);
                }
            }
            __syncthreads();

            {
                int nrs = rs + 2;
                int crs = (nrs < 9) ? nrs : nrs - 9;
                stage_A(sb, (rs + apar) & 1,
                        g_aggw16 + ((size_t)b * RS_ + crs) * O_ * C_, tid);
                if (rs == 2) stage_Brow(sb, b, y0 + 3, tid);   // slot of y0-1 (freed after rs=2)
                if (rs == 5) stage_Brow(sb, b, y0 + 4, tid);   // slot of y0   (freed after rs=5)
                CP_COMMIT();
            }
        }
        apar ^= 1;

        // ---- epilogue ----
        const int g = lane >> 2, t4 = lane & 3;
        const int yout = y0 + h;
        #pragma unroll
        for (int mt = 0; mt < 4; mt++) {
            int o_lo = wm * 64 + mt * 16 + g;
            float b_lo = g_aggb[b * O_ + o_lo];
            float b_hi = g_aggb[b * O_ + o_lo + 8];
            float* p_lo = out + ((size_t)(b * O_ + o_lo) * H_ + yout) * W_;
            float* p_hi = p_lo + (size_t)8 * H_ * W_;
            #pragma unroll
            for (int nt = 0; nt < 4; nt++) {
                int xp = nb + nt * 8 + t4 * 2;
                float2 vlo = make_float2(acc[mt][nt][0] + b_lo, acc[mt][nt][1] + b_lo);
                float2 vhi = make_float2(acc[mt][nt][2] + b_hi, acc[mt][nt][3] + b_hi);
                *(float2*)(p_lo + xp) = vlo;
                *(float2*)(p_hi + xp) = vhi;
            }
        }
    }
    CP_WAIT(0);
}

// ---------------- launch ----------------
extern "C" void kernel_launch(void* const* d_in, const int* in_sizes, int n_in,
                              void* d_out, int out_size) {
    const float* x      = (const float*)d_in[0];
    const float* att_w1 = (const float*)d_in[1];
    const float* att_b1 = (const float*)d_in[2];
    const float* att_w2 = (const float*)d_in[3];
    const float* att_b2 = (const float*)d_in[4];
    const float* weight = (const float*)d_in[5];
    const float* bias   = (const float*)d_in[6];
    float* out = (float*)d_out;

    cudaFuncSetAttribute(conv_hmma, cudaFuncAttributeMaxDynamicSharedMemorySize, SMEM_CONV);

    xT_kernel<<<B_ * H_, 256>>>(x);
    attn2_kernel<<<B_, 128>>>(att_w1, att_b1, att_w2, att_b2, bias);
    aggw16_kernel<<<dim3(64, B_), 256>>>(weight);
    conv_hmma<<<NCTA, 512, SMEM_CONV>>>(out);
}